// round 14
// baseline (speedup 1.0000x reference)
#include <cuda_runtime.h>
#include <math.h>

#define NN    14
#define SEQ   24
#define GH    64
#define E0    56
#define NE    70
#define BATCH 32768

// 44 MB intermediate in [node][batch][seq] layout (== output layout)
__device__ float g_mid[(size_t)NN * BATCH * SEQ];

// ---------------- f32x2 packed-math helpers (Blackwell FFMA2) ----------------
typedef unsigned long long u64;

__device__ __forceinline__ u64 pk2(float lo, float hi) {
    u64 r; asm("mov.b64 %0, {%1,%2};" : "=l"(r) : "f"(lo), "f"(hi)); return r;
}
__device__ __forceinline__ void upk2(u64 v, float& lo, float& hi) {
    asm("mov.b64 {%0,%1}, %2;" : "=f"(lo), "=f"(hi) : "l"(v));
}
__device__ __forceinline__ u64 ff2(u64 a, u64 b, u64 c) {   // {a.lo*b.lo+c.lo, a.hi*b.hi+c.hi}
    u64 d; asm("fma.rn.f32x2 %0, %1, %2, %3;" : "=l"(d) : "l"(a), "l"(b), "l"(c)); return d;
}

// ================================ GAT kernel =================================
#define WARPS_A 4
#define PW_SIZE 1208
#define BC_SIZE 3640
#define SH_FLOATS (BC_SIZE + WARPS_A * PW_SIZE)
#define SH_BYTES  (SH_FLOATS * 4)      // 33,888 B -> 5 blocks/SM (reg-limited), 20 warps

__global__ void __launch_bounds__(32 * WARPS_A)
gat_kernel(const float* __restrict__ x, const int* __restrict__ ei,
           const float* __restrict__ W1, const float* __restrict__ as1,
           const float* __restrict__ ad1, const float* __restrict__ b1,
           const float* __restrict__ W2, const float* __restrict__ as2,
           const float* __restrict__ ad2, const float* __restrict__ b2)
{
    extern __shared__ float sh[];
    u64*   sW1p  = (u64*)sh;            // 768 u64: {W1[s][l], W1[s][l+32]}      floats 0..1535
    u64*   sW1ad = (u64*)(sh + 1536);   // 24 u64: {W1·a_src1, W1·a_dst1}[s]     floats 1536..1583
    u64*   sW2p  = (u64*)(sh + 1584);   // [32][25] u64: {W2[2j][o],W2[2j+1][o]} floats 1584..3183
    float* sW2a  = sh + 3184;           // 64
    float* sW2d  = sh + 3248;           // 64
    float* sB1   = sh + 3312;           // 64
    float* sB2   = sh + 3376;           // 24
    float* sCnt  = sh + 3400;           // 14*17 = 238 (pad 240) -> 3640

    const int tid = threadIdx.x;

    // ---- phase A: bulk loads ----
    for (int i = tid; i < 768; i += blockDim.x) {
        int s_ = i >> 5, l = i & 31;
        sW1p[i] = pk2(W1[s_ * GH + l], W1[s_ * GH + 32 + l]);
    }
    for (int i = tid; i < 768; i += blockDim.x) {
        int j = i / 24, o = i - j * 24;
        sW2p[j * 25 + o] = pk2(W2[(2 * j) * SEQ + o], W2[(2 * j + 1) * SEQ + o]);
    }
    if (tid < 64) sB1[tid] = b1[tid];
    if (tid < 24) sB2[tid] = b2[tid];
    for (int i = tid; i < 240; i += blockDim.x) sCnt[i] = 0.f;
    __syncthreads();

    // ---- phase B: attention-vector precompute + edge-count matrix ----
    // (128-thread block: sub-tasks on threads 0-23, 24-87, 96-111)
    if (tid < 24) {
        float s_ = 0.f, d_ = 0.f;
        #pragma unroll
        for (int f = 0; f < GH; f++) {
            float w = W1[tid * GH + f];
            s_ += w * as1[f];
            d_ += w * ad1[f];
        }
        sW1ad[tid] = pk2(s_, d_);
    } else if (tid < 88) {
        int f = tid - 24;
        float s_ = 0.f, d_ = 0.f;
        #pragma unroll
        for (int o = 0; o < SEQ; o++) {
            float w = W2[f * SEQ + o];
            s_ += w * as2[o];
            d_ += w * ad2[o];
        }
        sW2a[f] = s_; sW2d[f] = d_;
    } else if (tid >= 96 && tid < 112) {
        for (int e = tid - 96; e < NE; e += 16) {
            int s_, d_;
            if (e < E0) { s_ = ei[e]; d_ = ei[E0 + e]; }
            else        { s_ = e - E0; d_ = s_; }
            atomicAdd(&sCnt[d_ * 17 + s_], 1.0f);
        }
    }
    __syncthreads();

    const int warp = tid >> 5, lane = tid & 31;
    const int b = blockIdx.x * WARPS_A + warp;
    if (b >= BATCH) return;

    float* pw  = sh + BC_SIZE + warp * PW_SIZE;
    u64*   xu  = (u64*)pw;      // [14][24] duplicated x  (dead after step 3)
    float* g1s = pw;            // [14][68] g1, later t   (overlays xu)
    float* Aw  = pw + 952;      // [14][16]
    float* vas = pw + 1176;     // 16
    float* vad = pw + 1192;     // 16

    // ---- 1. load x[b] -> duplicated transposed xu[n][s] = {x,x} ----
    {
        const float4* xb4 = (const float4*)(x + (size_t)b * (SEQ * NN));
        for (int i4 = lane; i4 < 84; i4 += 32) {
            float4 v = xb4[i4];
            int base = i4 * 4;
            int s0 = base / NN,       n0 = base - s0 * NN;
            int s1 = (base+1) / NN,   n1 = (base+1) - s1 * NN;
            int s2_ = (base+2) / NN,  n2 = (base+2) - s2_ * NN;
            int s3 = (base+3) / NN,   n3 = (base+3) - s3 * NN;
            xu[n0 * 24 + s0]  = pk2(v.x, v.x);
            xu[n1 * 24 + s1]  = pk2(v.y, v.y);
            xu[n2 * 24 + s2_] = pk2(v.z, v.z);
            xu[n3 * 24 + s3]  = pk2(v.w, v.w);
        }
    }
    __syncwarp();

    // ---- 2. layer-1 attention dots (packed, paired loads) ----
    if (lane < NN) {
        u64 acc = 0ull;
        #pragma unroll
        for (int s = 0; s < SEQ; s += 2) {
            ulonglong2 xx = *(const ulonglong2*)&xu[lane * 24 + s];
            ulonglong2 wv = *(const ulonglong2*)&sW1ad[s];
            acc = ff2(xx.x, wv.x, ff2(xx.y, wv.y, acc));
        }
        float a_, d_; upk2(acc, a_, d_);
        vas[lane] = a_; vad[lane] = d_;
    }

    // ---- 3. h1 packed in registers (paired s iterations) ----
    u64 h2[NN];
    #pragma unroll
    for (int n = 0; n < NN; n++) h2[n] = 0ull;
    #pragma unroll
    for (int s = 0; s < SEQ; s += 2) {
        u64 wv0 = sW1p[s * 32 + lane];
        u64 wv1 = sW1p[(s + 1) * 32 + lane];
        #pragma unroll
        for (int n = 0; n < NN; n++) {
            ulonglong2 xx = *(const ulonglong2*)&xu[n * 24 + s];
            h2[n] = ff2(xx.x, wv0, ff2(xx.y, wv1, h2[n]));
        }
    }
    float h1a[NN], h1b[NN];
    #pragma unroll
    for (int n = 0; n < NN; n++) upk2(h2[n], h1a[n], h1b[n]);
    __syncwarp();

    // ---- 4. softmax layer 1 -> Aw, vas := 1/sum ----
    if (lane < NN) {
        const float dn = vad[lane];
        float al[NN], mx = -1e30f;
        #pragma unroll
        for (int m = 0; m < NN; m++) {
            float c = sCnt[lane * 17 + m];
            float v = vas[m] + dn;
            v = (v >= 0.f) ? v : 0.2f * v;
            al[m] = v;
            if (c > 0.f) mx = fmaxf(mx, v);
        }
        float ssum = 0.f;
        #pragma unroll
        for (int m = 0; m < NN; m++) {
            float c = sCnt[lane * 17 + m];
            float e = c * __expf(al[m] - mx);
            ssum += e;
            Aw[lane * 16 + m] = e;
        }
        Aw[lane * 16 + 14] = 0.f;
        Aw[lane * 16 + 15] = 0.f;
        vas[lane] = 1.0f / ssum;
    }
    __syncwarp();

    // ---- 5. aggregate layer 1 + bias + ELU; stash g1 ----
    float g1a[NN], g1b[NN];
    {
        const float bb0 = sB1[lane], bb1 = sB1[32 + lane];
        #pragma unroll
        for (int n = 0; n < NN; n++) {
            float4 A0 = *(const float4*)&Aw[n * 16 + 0];
            float4 A1 = *(const float4*)&Aw[n * 16 + 4];
            float4 A2 = *(const float4*)&Aw[n * 16 + 8];
            float2 A3 = *(const float2*)&Aw[n * 16 + 12];
            float a0 = A0.x*h1a[0] + A0.y*h1a[1] + A0.z*h1a[2] + A0.w*h1a[3]
                     + A1.x*h1a[4] + A1.y*h1a[5] + A1.z*h1a[6] + A1.w*h1a[7]
                     + A2.x*h1a[8] + A2.y*h1a[9] + A2.z*h1a[10]+ A2.w*h1a[11]
                     + A3.x*h1a[12]+ A3.y*h1a[13];
            float a1 = A0.x*h1b[0] + A0.y*h1b[1] + A0.z*h1b[2] + A0.w*h1b[3]
                     + A1.x*h1b[4] + A1.y*h1b[5] + A1.z*h1b[6] + A1.w*h1b[7]
                     + A2.x*h1b[8] + A2.y*h1b[9] + A2.z*h1b[10]+ A2.w*h1b[11]
                     + A3.x*h1b[12]+ A3.y*h1b[13];
            float inv = vas[n];
            float v0 = a0 * inv + bb0;
            float v1 = a1 * inv + bb1;
            v0 = (v0 > 0.f) ? v0 : (__expf(v0) - 1.f);
            v1 = (v1 > 0.f) ? v1 : (__expf(v1) - 1.f);
            g1a[n] = v0; g1b[n] = v1;
            g1s[n * 68 + lane]      = v0;
            g1s[n * 68 + 32 + lane] = v1;
        }
    }
    __syncwarp();

    // ---- 6. layer-2 attention dots ----
    if (lane < NN) {
        float s_ = 0.f, d_ = 0.f;
        #pragma unroll
        for (int j = 0; j < 16; j++) {
            float4 g = *(const float4*)&g1s[lane * 68 + 4 * j];
            float4 wa = *(const float4*)&sW2a[4 * j];
            float4 wd = *(const float4*)&sW2d[4 * j];
            s_ += g.x * wa.x + g.y * wa.y + g.z * wa.z + g.w * wa.w;
            d_ += g.x * wd.x + g.y * wd.y + g.z * wd.z + g.w * wd.w;
        }
        vas[lane] = s_; vad[lane] = d_;
    }
    __syncwarp();

    // ---- 7. softmax layer 2 -> Aw, vas := 1/sum ----
    if (lane < NN) {
        const float dn = vad[lane];
        float al[NN], mx = -1e30f;
        #pragma unroll
        for (int m = 0; m < NN; m++) {
            float c = sCnt[lane * 17 + m];
            float v = vas[m] + dn;
            v = (v >= 0.f) ? v : 0.2f * v;
            al[m] = v;
            if (c > 0.f) mx = fmaxf(mx, v);
        }
        float ssum = 0.f;
        #pragma unroll
        for (int m = 0; m < NN; m++) {
            float c = sCnt[lane * 17 + m];
            float e = c * __expf(al[m] - mx);
            ssum += e;
            Aw[lane * 16 + m] = e;
        }
        Aw[lane * 16 + 14] = 0.f;
        Aw[lane * 16 + 15] = 0.f;
        vas[lane] = 1.0f / ssum;
    }
    __syncwarp();

    // ---- 8. t = A2·g1 (registers), scaled; stash ----
    #pragma unroll
    for (int n = 0; n < NN; n++) {
        float4 A0 = *(const float4*)&Aw[n * 16 + 0];
        float4 A1 = *(const float4*)&Aw[n * 16 + 4];
        float4 A2 = *(const float4*)&Aw[n * 16 + 8];
        float2 A3 = *(const float2*)&Aw[n * 16 + 12];
        float a0 = A0.x*g1a[0] + A0.y*g1a[1] + A0.z*g1a[2] + A0.w*g1a[3]
                 + A1.x*g1a[4] + A1.y*g1a[5] + A1.z*g1a[6] + A1.w*g1a[7]
                 + A2.x*g1a[8] + A2.y*g1a[9] + A2.z*g1a[10]+ A2.w*g1a[11]
                 + A3.x*g1a[12]+ A3.y*g1a[13];
        float a1 = A0.x*g1b[0] + A0.y*g1b[1] + A0.z*g1b[2] + A0.w*g1b[3]
                 + A1.x*g1b[4] + A1.y*g1b[5] + A1.z*g1b[6] + A1.w*g1b[7]
                 + A2.x*g1b[8] + A2.y*g1b[9] + A2.z*g1b[10]+ A2.w*g1b[11]
                 + A3.x*g1b[12]+ A3.y*g1b[13];
        float inv = vas[n];
        g1s[n * 68 + lane]      = a0 * inv;
        g1s[n * 68 + 32 + lane] = a1 * inv;
    }
    __syncwarp();

    // ---- 9. g2 = t·W2 + b2 -> g_mid[n][b][o] (packed FFMA2, broadcast weights) ----
    {
        const int o = (lane < SEQ) ? lane : 0;
        u64 acc2[NN];
        #pragma unroll
        for (int n = 0; n < NN; n++) acc2[n] = 0ull;
        #pragma unroll
        for (int c = 0; c < 4; c++) {
            u64 w2r[8];
            #pragma unroll
            for (int j = 0; j < 8; j++) w2r[j] = sW2p[(c * 8 + j) * 25 + o];
            #pragma unroll
            for (int n = 0; n < NN; n++) {
                const ulonglong2* tp = (const ulonglong2*)&g1s[n * 68 + c * 16];
                ulonglong2 t0 = tp[0], t1 = tp[1], t2 = tp[2], t3 = tp[3];
                u64 a = acc2[n];
                a = ff2(t0.x, w2r[0], a); a = ff2(t0.y, w2r[1], a);
                a = ff2(t1.x, w2r[2], a); a = ff2(t1.y, w2r[3], a);
                a = ff2(t2.x, w2r[4], a); a = ff2(t2.y, w2r[5], a);
                a = ff2(t3.x, w2r[6], a); a = ff2(t3.y, w2r[7], a);
                acc2[n] = a;
            }
        }
        if (lane < SEQ) {
            const float bb2 = sB2[o];
            #pragma unroll
            for (int n = 0; n < NN; n++) {
                float lo, hi; upk2(acc2[n], lo, hi);
                g_mid[(size_t)n * BATCH * SEQ + (size_t)b * SEQ + lane] = lo + hi + bb2;
            }
        }
    }
}

// ============================ MLP kernel (round-8 exact, 120.6 us) ===========
#define MW 4
#define MLP_SMEM_U64 (1600 + 1536 + 24 + MW * 800)
#define MLP_SMEM_BYTES (MLP_SMEM_U64 * 8)    // 50,880 B

__global__ void __launch_bounds__(32 * MW, 4)
mlp_kernel(const float* __restrict__ f1w, const float* __restrict__ f1b,
           const float* __restrict__ f2w, const float* __restrict__ f2b,
           float* __restrict__ out)
{
    extern __shared__ u64 dsm[];
    u64* sw1 = dsm;              // [25][64]: s rows duplicated {w,w}; row 24 = {b1,b1}
    u64* sw2 = dsm + 1600;       // [64][24]: {w2[f][o], w2[f][o]}
    u64* sb2 = dsm + 3136;       // 24: {b2[o], b2[o]}

    const int n   = blockIdx.y;
    const int tid = threadIdx.x;

    const float* w1base = f1w + (size_t)n * SEQ * GH;
    for (int i = tid; i < SEQ * GH; i += 32 * MW) { float v = w1base[i]; sw1[i] = pk2(v, v); }
    const float* b1base = f1b + (size_t)n * GH;
    for (int i = tid; i < GH; i += 32 * MW)       { float v = b1base[i]; sw1[24 * 64 + i] = pk2(v, v); }
    const float* w2base = f2w + (size_t)n * GH * SEQ;
    for (int i = tid; i < GH * SEQ; i += 32 * MW) { float v = w2base[i]; sw2[i] = pk2(v, v); }
    if (tid < SEQ) { float v = f2b[(size_t)n * SEQ + tid]; sb2[tid] = pk2(v, v); }
    __syncthreads();

    const int warp = tid >> 5, lane = tid & 31;
    u64* gp = dsm + 3160 + warp * 800;       // [32][25] packed g, self-row only

    const int base = (blockIdx.x * MW + warp) * 64;
    const float* gb = g_mid + (size_t)n * BATCH * SEQ;

    {
        const float4* r0 = (const float4*)(gb + (size_t)(base + lane) * SEQ);
        const float4* r1 = (const float4*)(gb + (size_t)(base + 32 + lane) * SEQ);
        u64* gr = gp + lane * 25;
        #pragma unroll
        for (int j = 0; j < 6; j++) {
            float4 a = r0[j], c = r1[j];
            gr[4 * j + 0] = pk2(a.x, c.x);
            gr[4 * j + 1] = pk2(a.y, c.y);
            gr[4 * j + 2] = pk2(a.z, c.z);
            gr[4 * j + 3] = pk2(a.w, c.w);
        }
    }

    u64 acc[SEQ];
    #pragma unroll
    for (int o = 0; o < SEQ; o++) acc[o] = sb2[o];

    const u64* gr = gp + lane * 25;

    #pragma unroll 1
    for (int c = 0; c < 8; c++) {
        u64 h[8];
        #pragma unroll
        for (int j = 0; j < 4; j++) {
            ulonglong2 bb = *(const ulonglong2*)&sw1[24 * 64 + c * 8 + 2 * j];
            h[2 * j] = bb.x; h[2 * j + 1] = bb.y;
        }
        #pragma unroll
        for (int s = 0; s < SEQ; s++) {
            u64 gv = gr[s];
            #pragma unroll
            for (int j = 0; j < 4; j++) {
                ulonglong2 w = *(const ulonglong2*)&sw1[s * 64 + c * 8 + 2 * j];
                h[2 * j]     = ff2(gv, w.x, h[2 * j]);
                h[2 * j + 1] = ff2(gv, w.y, h[2 * j + 1]);
            }
        }
        #pragma unroll
        for (int j = 0; j < 8; j++) {
            float lo, hi; upk2(h[j], lo, hi);
            h[j] = pk2(fmaxf(lo, 0.f), fmaxf(hi, 0.f));
        }
        #pragma unroll
        for (int j = 0; j < 8; j++) {
            const int f = c * 8 + j;
            #pragma unroll
            for (int oo = 0; oo < 12; oo++) {
                ulonglong2 w = *(const ulonglong2*)&sw2[f * 24 + 2 * oo];
                acc[2 * oo]     = ff2(h[j], w.x, acc[2 * oo]);
                acc[2 * oo + 1] = ff2(h[j], w.y, acc[2 * oo + 1]);
            }
        }
    }

    float* ob0 = out + (size_t)n * BATCH * SEQ + (size_t)(base + lane) * SEQ;
    float* ob1 = ob0 + (size_t)32 * SEQ;
    #pragma unroll
    for (int j = 0; j < 6; j++) {
        float a0,a1,b0,b1v,c0,c1,d0,d1;
        upk2(acc[4*j+0], a0, a1);
        upk2(acc[4*j+1], b0, b1v);
        upk2(acc[4*j+2], c0, c1);
        upk2(acc[4*j+3], d0, d1);
        ((float4*)ob0)[j] = make_float4(a0, b0, c0, d0);
        ((float4*)ob1)[j] = make_float4(a1, b1v, c1, d1);
    }
}

extern "C" void kernel_launch(void* const* d_in, const int* in_sizes, int n_in,
                              void* d_out, int out_size)
{
    const float* x   = (const float*)d_in[0];
    const int*   ei  = (const int*)d_in[1];
    const float* W1  = (const float*)d_in[2];
    const float* as1 = (const float*)d_in[3];
    const float* ad1 = (const float*)d_in[4];
    const float* b1  = (const float*)d_in[5];
    const float* W2  = (const float*)d_in[6];
    const float* as2 = (const float*)d_in[7];
    const float* ad2 = (const float*)d_in[8];
    const float* b2  = (const float*)d_in[9];
    const float* f1w = (const float*)d_in[10];
    const float* f1b = (const float*)d_in[11];
    const float* f2w = (const float*)d_in[12];
    const float* f2b = (const float*)d_in[13];
    float* out = (float*)d_out;

    static int configured = 0;
    if (!configured) {
        cudaFuncSetAttribute((const void*)mlp_kernel,
                             cudaFuncAttributeMaxDynamicSharedMemorySize, MLP_SMEM_BYTES);
        configured = 1;
    }

    gat_kernel<<<(BATCH + WARPS_A - 1) / WARPS_A, 32 * WARPS_A, SH_BYTES>>>(
        x, ei, W1, as1, ad1, b1, W2, as2, ad2, b2);

    mlp_kernel<<<dim3(BATCH / (MW * 64), NN), 32 * MW, MLP_SMEM_BYTES>>>(
        f1w, f1b, f2w, f2b, out);
}

// round 15
// speedup vs baseline: 1.0256x; 1.0256x over previous
#include <cuda_runtime.h>
#include <math.h>

#define NN    14
#define SEQ   24
#define GH    64
#define E0    56
#define NE    70
#define BATCH 32768

// 44 MB intermediate in [node][batch][seq] layout (== output layout)
__device__ float g_mid[(size_t)NN * BATCH * SEQ];

// ---------------- f32x2 packed-math helpers (Blackwell FFMA2) ----------------
typedef unsigned long long u64;

__device__ __forceinline__ u64 pk2(float lo, float hi) {
    u64 r; asm("mov.b64 %0, {%1,%2};" : "=l"(r) : "f"(lo), "f"(hi)); return r;
}
__device__ __forceinline__ void upk2(u64 v, float& lo, float& hi) {
    asm("mov.b64 {%0,%1}, %2;" : "=f"(lo), "=f"(hi) : "l"(v));
}
__device__ __forceinline__ u64 ff2(u64 a, u64 b, u64 c) {   // {a.lo*b.lo+c.lo, a.hi*b.hi+c.hi}
    u64 d; asm("fma.rn.f32x2 %0, %1, %2, %3;" : "=l"(d) : "l"(a), "l"(b), "l"(c)); return d;
}

// ================================ GAT kernel =================================
#define WARPS_A 6
#define PW_SIZE 1208
#define BC_SIZE 3640
#define SH_FLOATS (BC_SIZE + WARPS_A * PW_SIZE)
#define SH_BYTES  (SH_FLOATS * 4)      // 43,552 B < 48 KB
#define GAT_UNITS   ((BATCH + WARPS_A - 1) / WARPS_A)   // 5462
#define GAT_NBLOCKS 5328               // = 444*12 = 592*9 (wave-exact @3 or 4 blocks/SM)

__global__ void __launch_bounds__(32 * WARPS_A)
gat_kernel(const float* __restrict__ x, const int* __restrict__ ei,
           const float* __restrict__ W1, const float* __restrict__ as1,
           const float* __restrict__ ad1, const float* __restrict__ b1,
           const float* __restrict__ W2, const float* __restrict__ as2,
           const float* __restrict__ ad2, const float* __restrict__ b2)
{
    extern __shared__ float sh[];
    u64*   sW1p  = (u64*)sh;            // 768 u64: {W1[s][l], W1[s][l+32]}      floats 0..1535
    u64*   sW1ad = (u64*)(sh + 1536);   // 24 u64: {W1·a_src1, W1·a_dst1}[s]     floats 1536..1583
    u64*   sW2p  = (u64*)(sh + 1584);   // [32][25] u64: {W2[2j][o],W2[2j+1][o]} floats 1584..3183
    float* sW2a  = sh + 3184;           // 64
    float* sW2d  = sh + 3248;           // 64
    float* sB1   = sh + 3312;           // 64
    float* sB2   = sh + 3376;           // 24
    float* sCnt  = sh + 3400;           // 14*17 = 238 (pad 240) -> 3640

    const int tid = threadIdx.x;

    // ---- phase A: bulk loads (once per block) ----
    for (int i = tid; i < 768; i += blockDim.x) {
        int s_ = i >> 5, l = i & 31;
        sW1p[i] = pk2(W1[s_ * GH + l], W1[s_ * GH + 32 + l]);
    }
    for (int i = tid; i < 768; i += blockDim.x) {
        int j = i / 24, o = i - j * 24;
        sW2p[j * 25 + o] = pk2(W2[(2 * j) * SEQ + o], W2[(2 * j + 1) * SEQ + o]);
    }
    if (tid < 64) sB1[tid] = b1[tid];
    if (tid < 24) sB2[tid] = b2[tid];
    for (int i = tid; i < 240; i += blockDim.x) sCnt[i] = 0.f;
    __syncthreads();

    // ---- phase B: attention-vector precompute + edge-count matrix ----
    if (tid < 24) {
        float s_ = 0.f, d_ = 0.f;
        #pragma unroll
        for (int f = 0; f < GH; f++) {
            float w = W1[tid * GH + f];
            s_ += w * as1[f];
            d_ += w * ad1[f];
        }
        sW1ad[tid] = pk2(s_, d_);
    } else if (tid < 88) {
        int f = tid - 24;
        float s_ = 0.f, d_ = 0.f;
        #pragma unroll
        for (int o = 0; o < SEQ; o++) {
            float w = W2[f * SEQ + o];
            s_ += w * as2[o];
            d_ += w * ad2[o];
        }
        sW2a[f] = s_; sW2d[f] = d_;
    } else if (tid >= 176) {
        for (int e = tid - 176; e < NE; e += 16) {
            int s_, d_;
            if (e < E0) { s_ = ei[e]; d_ = ei[E0 + e]; }
            else        { s_ = e - E0; d_ = s_; }
            atomicAdd(&sCnt[d_ * 17 + s_], 1.0f);
        }
    }
    __syncthreads();

    const int warp = tid >> 5, lane = tid & 31;
    float* pw  = sh + BC_SIZE + warp * PW_SIZE;
    u64*   xu  = (u64*)pw;      // [14][24] duplicated x  (dead after step 3)
    float* g1s = pw;            // [14][68] g1, later t   (overlays xu)
    float* Aw  = pw + 952;      // [14][16]
    float* vas = pw + 1176;     // 16
    float* vad = pw + 1192;     // 16

    // ---- wave-aligned grid-stride over sample units (weights stay staged) ----
    for (int unit = blockIdx.x; unit < GAT_UNITS; unit += GAT_NBLOCKS) {
        const int b = unit * WARPS_A + warp;
        if (b < BATCH) {

        // ---- 1. load x[b] -> duplicated transposed xu[n][s] = {x,x} ----
        {
            const float4* xb4 = (const float4*)(x + (size_t)b * (SEQ * NN));
            for (int i4 = lane; i4 < 84; i4 += 32) {
                float4 v = xb4[i4];
                int base = i4 * 4;
                int s0 = base / NN,       n0 = base - s0 * NN;
                int s1 = (base+1) / NN,   n1 = (base+1) - s1 * NN;
                int s2_ = (base+2) / NN,  n2 = (base+2) - s2_ * NN;
                int s3 = (base+3) / NN,   n3 = (base+3) - s3 * NN;
                xu[n0 * 24 + s0]  = pk2(v.x, v.x);
                xu[n1 * 24 + s1]  = pk2(v.y, v.y);
                xu[n2 * 24 + s2_] = pk2(v.z, v.z);
                xu[n3 * 24 + s3]  = pk2(v.w, v.w);
            }
        }
        __syncwarp();

        // ---- 2. layer-1 attention dots (packed, paired loads) ----
        if (lane < NN) {
            u64 acc = 0ull;
            #pragma unroll
            for (int s = 0; s < SEQ; s += 2) {
                ulonglong2 xx = *(const ulonglong2*)&xu[lane * 24 + s];
                ulonglong2 wv = *(const ulonglong2*)&sW1ad[s];
                acc = ff2(xx.x, wv.x, ff2(xx.y, wv.y, acc));
            }
            float a_, d_; upk2(acc, a_, d_);
            vas[lane] = a_; vad[lane] = d_;
        }

        // ---- 3. h1 packed in registers (paired s iterations) ----
        u64 h2[NN];
        #pragma unroll
        for (int n = 0; n < NN; n++) h2[n] = 0ull;
        #pragma unroll
        for (int s = 0; s < SEQ; s += 2) {
            u64 wv0 = sW1p[s * 32 + lane];
            u64 wv1 = sW1p[(s + 1) * 32 + lane];
            #pragma unroll
            for (int n = 0; n < NN; n++) {
                ulonglong2 xx = *(const ulonglong2*)&xu[n * 24 + s];
                h2[n] = ff2(xx.x, wv0, ff2(xx.y, wv1, h2[n]));
            }
        }
        float h1a[NN], h1b[NN];
        #pragma unroll
        for (int n = 0; n < NN; n++) upk2(h2[n], h1a[n], h1b[n]);
        __syncwarp();

        // ---- 4. softmax layer 1 -> Aw, vas := 1/sum ----
        if (lane < NN) {
            const float dn = vad[lane];
            float al[NN], mx = -1e30f;
            #pragma unroll
            for (int m = 0; m < NN; m++) {
                float c = sCnt[lane * 17 + m];
                float v = vas[m] + dn;
                v = (v >= 0.f) ? v : 0.2f * v;
                al[m] = v;
                if (c > 0.f) mx = fmaxf(mx, v);
            }
            float ssum = 0.f;
            #pragma unroll
            for (int m = 0; m < NN; m++) {
                float c = sCnt[lane * 17 + m];
                float e = c * __expf(al[m] - mx);
                ssum += e;
                Aw[lane * 16 + m] = e;
            }
            Aw[lane * 16 + 14] = 0.f;
            Aw[lane * 16 + 15] = 0.f;
            vas[lane] = 1.0f / ssum;
        }
        __syncwarp();

        // ---- 5. aggregate layer 1 + bias + ELU; stash g1 ----
        float g1a[NN], g1b[NN];
        {
            const float bb0 = sB1[lane], bb1 = sB1[32 + lane];
            #pragma unroll
            for (int n = 0; n < NN; n++) {
                float4 A0 = *(const float4*)&Aw[n * 16 + 0];
                float4 A1 = *(const float4*)&Aw[n * 16 + 4];
                float4 A2 = *(const float4*)&Aw[n * 16 + 8];
                float2 A3 = *(const float2*)&Aw[n * 16 + 12];
                float a0 = A0.x*h1a[0] + A0.y*h1a[1] + A0.z*h1a[2] + A0.w*h1a[3]
                         + A1.x*h1a[4] + A1.y*h1a[5] + A1.z*h1a[6] + A1.w*h1a[7]
                         + A2.x*h1a[8] + A2.y*h1a[9] + A2.z*h1a[10]+ A2.w*h1a[11]
                         + A3.x*h1a[12]+ A3.y*h1a[13];
                float a1 = A0.x*h1b[0] + A0.y*h1b[1] + A0.z*h1b[2] + A0.w*h1b[3]
                         + A1.x*h1b[4] + A1.y*h1b[5] + A1.z*h1b[6] + A1.w*h1b[7]
                         + A2.x*h1b[8] + A2.y*h1b[9] + A2.z*h1b[10]+ A2.w*h1b[11]
                         + A3.x*h1b[12]+ A3.y*h1b[13];
                float inv = vas[n];
                float v0 = a0 * inv + bb0;
                float v1 = a1 * inv + bb1;
                v0 = (v0 > 0.f) ? v0 : (__expf(v0) - 1.f);
                v1 = (v1 > 0.f) ? v1 : (__expf(v1) - 1.f);
                g1a[n] = v0; g1b[n] = v1;
                g1s[n * 68 + lane]      = v0;
                g1s[n * 68 + 32 + lane] = v1;
            }
        }
        __syncwarp();

        // ---- 6. layer-2 attention dots ----
        if (lane < NN) {
            float s_ = 0.f, d_ = 0.f;
            #pragma unroll
            for (int j = 0; j < 16; j++) {
                float4 g = *(const float4*)&g1s[lane * 68 + 4 * j];
                float4 wa = *(const float4*)&sW2a[4 * j];
                float4 wd = *(const float4*)&sW2d[4 * j];
                s_ += g.x * wa.x + g.y * wa.y + g.z * wa.z + g.w * wa.w;
                d_ += g.x * wd.x + g.y * wd.y + g.z * wd.z + g.w * wd.w;
            }
            vas[lane] = s_; vad[lane] = d_;
        }
        __syncwarp();

        // ---- 7. softmax layer 2 -> Aw, vas := 1/sum ----
        if (lane < NN) {
            const float dn = vad[lane];
            float al[NN], mx = -1e30f;
            #pragma unroll
            for (int m = 0; m < NN; m++) {
                float c = sCnt[lane * 17 + m];
                float v = vas[m] + dn;
                v = (v >= 0.f) ? v : 0.2f * v;
                al[m] = v;
                if (c > 0.f) mx = fmaxf(mx, v);
            }
            float ssum = 0.f;
            #pragma unroll
            for (int m = 0; m < NN; m++) {
                float c = sCnt[lane * 17 + m];
                float e = c * __expf(al[m] - mx);
                ssum += e;
                Aw[lane * 16 + m] = e;
            }
            Aw[lane * 16 + 14] = 0.f;
            Aw[lane * 16 + 15] = 0.f;
            vas[lane] = 1.0f / ssum;
        }
        __syncwarp();

        // ---- 8. t = A2·g1 (registers), scaled; stash ----
        #pragma unroll
        for (int n = 0; n < NN; n++) {
            float4 A0 = *(const float4*)&Aw[n * 16 + 0];
            float4 A1 = *(const float4*)&Aw[n * 16 + 4];
            float4 A2 = *(const float4*)&Aw[n * 16 + 8];
            float2 A3 = *(const float2*)&Aw[n * 16 + 12];
            float a0 = A0.x*g1a[0] + A0.y*g1a[1] + A0.z*g1a[2] + A0.w*g1a[3]
                     + A1.x*g1a[4] + A1.y*g1a[5] + A1.z*g1a[6] + A1.w*g1a[7]
                     + A2.x*g1a[8] + A2.y*g1a[9] + A2.z*g1a[10]+ A2.w*g1a[11]
                     + A3.x*g1a[12]+ A3.y*g1a[13];
            float a1 = A0.x*g1b[0] + A0.y*g1b[1] + A0.z*g1b[2] + A0.w*g1b[3]
                     + A1.x*g1b[4] + A1.y*g1b[5] + A1.z*g1b[6] + A1.w*g1b[7]
                     + A2.x*g1b[8] + A2.y*g1b[9] + A2.z*g1b[10]+ A2.w*g1b[11]
                     + A3.x*g1b[12]+ A3.y*g1b[13];
            float inv = vas[n];
            g1s[n * 68 + lane]      = a0 * inv;
            g1s[n * 68 + 32 + lane] = a1 * inv;
        }
        __syncwarp();

        // ---- 9. g2 = t·W2 + b2 -> g_mid[n][b][o] (packed FFMA2) ----
        {
            const int o = (lane < SEQ) ? lane : 0;
            u64 acc2[NN];
            #pragma unroll
            for (int n = 0; n < NN; n++) acc2[n] = 0ull;
            #pragma unroll
            for (int c = 0; c < 4; c++) {
                u64 w2r[8];
                #pragma unroll
                for (int j = 0; j < 8; j++) w2r[j] = sW2p[(c * 8 + j) * 25 + o];
                #pragma unroll
                for (int n = 0; n < NN; n++) {
                    const ulonglong2* tp = (const ulonglong2*)&g1s[n * 68 + c * 16];
                    ulonglong2 t0 = tp[0], t1 = tp[1], t2 = tp[2], t3 = tp[3];
                    u64 a = acc2[n];
                    a = ff2(t0.x, w2r[0], a); a = ff2(t0.y, w2r[1], a);
                    a = ff2(t1.x, w2r[2], a); a = ff2(t1.y, w2r[3], a);
                    a = ff2(t2.x, w2r[4], a); a = ff2(t2.y, w2r[5], a);
                    a = ff2(t3.x, w2r[6], a); a = ff2(t3.y, w2r[7], a);
                    acc2[n] = a;
                }
            }
            if (lane < SEQ) {
                const float bb2 = sB2[o];
                #pragma unroll
                for (int n = 0; n < NN; n++) {
                    float lo, hi; upk2(acc2[n], lo, hi);
                    g_mid[(size_t)n * BATCH * SEQ + (size_t)b * SEQ + lane] = lo + hi + bb2;
                }
            }
        }
        __syncwarp();
        } // b < BATCH
    } // unit loop
}

// ============================ MLP kernel (round-8 body, wave-aligned) ========
#define MW 4
#define MLP_SMEM_U64 (1600 + 1536 + 24 + MW * 800)
#define MLP_SMEM_BYTES (MLP_SMEM_U64 * 8)    // 50,880 B
#define MLP_UNITS   (NN * (BATCH / (MW * 64)))   // 14 * 128 = 1792
#define MLP_NBLOCKS 1776                          // = 592 * 3 (wave-exact @4 blocks/SM)

__global__ void __launch_bounds__(32 * MW, 4)
mlp_kernel(const float* __restrict__ f1w, const float* __restrict__ f1b,
           const float* __restrict__ f2w, const float* __restrict__ f2b,
           float* __restrict__ out)
{
    extern __shared__ u64 dsm[];
    u64* sw1 = dsm;              // [25][64]: s rows duplicated {w,w}; row 24 = {b1,b1}
    u64* sw2 = dsm + 1600;       // [64][24]: {w2[f][o], w2[f][o]}
    u64* sb2 = dsm + 3136;       // 24: {b2[o], b2[o]}

    const int tid  = threadIdx.x;
    const int warp = tid >> 5, lane = tid & 31;
    u64* gp = dsm + 3160 + warp * 800;       // [32][25] packed g, self-row only

    for (int u = blockIdx.x; u < MLP_UNITS; u += MLP_NBLOCKS) {
        const int n     = u >> 7;        // u / 128
        const int chunk = u & 127;       // u % 128

        __syncthreads();   // all warps done with previous unit's weights

        const float* w1base = f1w + (size_t)n * SEQ * GH;
        for (int i = tid; i < SEQ * GH; i += 32 * MW) { float v = w1base[i]; sw1[i] = pk2(v, v); }
        const float* b1base = f1b + (size_t)n * GH;
        for (int i = tid; i < GH; i += 32 * MW)       { float v = b1base[i]; sw1[24 * 64 + i] = pk2(v, v); }
        const float* w2base = f2w + (size_t)n * GH * SEQ;
        for (int i = tid; i < GH * SEQ; i += 32 * MW) { float v = w2base[i]; sw2[i] = pk2(v, v); }
        if (tid < SEQ) { float v = f2b[(size_t)n * SEQ + tid]; sb2[tid] = pk2(v, v); }
        __syncthreads();

        const int base = (chunk * MW + warp) * 64;
        const float* gb = g_mid + (size_t)n * BATCH * SEQ;

        {
            const float4* r0 = (const float4*)(gb + (size_t)(base + lane) * SEQ);
            const float4* r1 = (const float4*)(gb + (size_t)(base + 32 + lane) * SEQ);
            u64* gr = gp + lane * 25;
            #pragma unroll
            for (int j = 0; j < 6; j++) {
                float4 a = r0[j], c = r1[j];
                gr[4 * j + 0] = pk2(a.x, c.x);
                gr[4 * j + 1] = pk2(a.y, c.y);
                gr[4 * j + 2] = pk2(a.z, c.z);
                gr[4 * j + 3] = pk2(a.w, c.w);
            }
        }

        u64 acc[SEQ];
        #pragma unroll
        for (int o = 0; o < SEQ; o++) acc[o] = sb2[o];

        const u64* gr = gp + lane * 25;

        #pragma unroll 1
        for (int c = 0; c < 8; c++) {
            u64 h[8];
            #pragma unroll
            for (int j = 0; j < 4; j++) {
                ulonglong2 bb = *(const ulonglong2*)&sw1[24 * 64 + c * 8 + 2 * j];
                h[2 * j] = bb.x; h[2 * j + 1] = bb.y;
            }
            #pragma unroll
            for (int s = 0; s < SEQ; s++) {
                u64 gv = gr[s];
                #pragma unroll
                for (int j = 0; j < 4; j++) {
                    ulonglong2 w = *(const ulonglong2*)&sw1[s * 64 + c * 8 + 2 * j];
                    h[2 * j]     = ff2(gv, w.x, h[2 * j]);
                    h[2 * j + 1] = ff2(gv, w.y, h[2 * j + 1]);
                }
            }
            #pragma unroll
            for (int j = 0; j < 8; j++) {
                float lo, hi; upk2(h[j], lo, hi);
                h[j] = pk2(fmaxf(lo, 0.f), fmaxf(hi, 0.f));
            }
            #pragma unroll
            for (int j = 0; j < 8; j++) {
                const int f = c * 8 + j;
                #pragma unroll
                for (int oo = 0; oo < 12; oo++) {
                    ulonglong2 w = *(const ulonglong2*)&sw2[f * 24 + 2 * oo];
                    acc[2 * oo]     = ff2(h[j], w.x, acc[2 * oo]);
                    acc[2 * oo + 1] = ff2(h[j], w.y, acc[2 * oo + 1]);
                }
            }
        }

        float* ob0 = out + (size_t)n * BATCH * SEQ + (size_t)(base + lane) * SEQ;
        float* ob1 = ob0 + (size_t)32 * SEQ;
        #pragma unroll
        for (int j = 0; j < 6; j++) {
            float a0,a1,b0v,b1v,c0,c1,d0,d1;
            upk2(acc[4*j+0], a0, a1);
            upk2(acc[4*j+1], b0v, b1v);
            upk2(acc[4*j+2], c0, c1);
            upk2(acc[4*j+3], d0, d1);
            ((float4*)ob0)[j] = make_float4(a0, b0v, c0, d0);
            ((float4*)ob1)[j] = make_float4(a1, b1v, c1, d1);
        }
    }
}

extern "C" void kernel_launch(void* const* d_in, const int* in_sizes, int n_in,
                              void* d_out, int out_size)
{
    const float* x   = (const float*)d_in[0];
    const int*   ei  = (const int*)d_in[1];
    const float* W1  = (const float*)d_in[2];
    const float* as1 = (const float*)d_in[3];
    const float* ad1 = (const float*)d_in[4];
    const float* b1  = (const float*)d_in[5];
    const float* W2  = (const float*)d_in[6];
    const float* as2 = (const float*)d_in[7];
    const float* ad2 = (const float*)d_in[8];
    const float* b2  = (const float*)d_in[9];
    const float* f1w = (const float*)d_in[10];
    const float* f1b = (const float*)d_in[11];
    const float* f2w = (const float*)d_in[12];
    const float* f2b = (const float*)d_in[13];
    float* out = (float*)d_out;

    static int configured = 0;
    if (!configured) {
        cudaFuncSetAttribute((const void*)mlp_kernel,
                             cudaFuncAttributeMaxDynamicSharedMemorySize, MLP_SMEM_BYTES);
        configured = 1;
    }

    gat_kernel<<<GAT_NBLOCKS, 32 * WARPS_A, SH_BYTES>>>(
        x, ei, W1, as1, ad1, b1, W2, as2, ad2, b2);

    mlp_kernel<<<MLP_NBLOCKS, 32 * MW, MLP_SMEM_BYTES>>>(
        f1w, f1b, f2w, f2b, out);
}

// round 16
// speedup vs baseline: 1.0653x; 1.0387x over previous
#include <cuda_runtime.h>
#include <math.h>

#define NN    14
#define SEQ   24
#define GH    64
#define E0    56
#define NE    70
#define BATCH 32768

// 44 MB intermediate in [node][batch][seq] layout (== output layout)
__device__ float g_mid[(size_t)NN * BATCH * SEQ];

// ---------------- f32x2 packed-math helpers (Blackwell FFMA2) ----------------
typedef unsigned long long u64;

__device__ __forceinline__ u64 pk2(float lo, float hi) {
    u64 r; asm("mov.b64 %0, {%1,%2};" : "=l"(r) : "f"(lo), "f"(hi)); return r;
}
__device__ __forceinline__ void upk2(u64 v, float& lo, float& hi) {
    asm("mov.b64 {%0,%1}, %2;" : "=f"(lo), "=f"(hi) : "l"(v));
}
__device__ __forceinline__ u64 ff2(u64 a, u64 b, u64 c) {   // {a.lo*b.lo+c.lo, a.hi*b.hi+c.hi}
    u64 d; asm("fma.rn.f32x2 %0, %1, %2, %3;" : "=l"(d) : "l"(a), "l"(b), "l"(c)); return d;
}

// ================================ GAT kernel =================================
#define WARPS_A 6
#define PW_SIZE 1208
#define BC_SIZE 3640
#define SH_FLOATS (BC_SIZE + WARPS_A * PW_SIZE)
#define SH_BYTES  (SH_FLOATS * 4)      // 43,552 B < 48 KB

__global__ void __launch_bounds__(32 * WARPS_A)
gat_kernel(const float* __restrict__ x, const int* __restrict__ ei,
           const float* __restrict__ W1, const float* __restrict__ as1,
           const float* __restrict__ ad1, const float* __restrict__ b1,
           const float* __restrict__ W2, const float* __restrict__ as2,
           const float* __restrict__ ad2, const float* __restrict__ b2)
{
    extern __shared__ float sh[];
    u64*   sW1p  = (u64*)sh;            // 768 u64: {W1[s][l], W1[s][l+32]}      floats 0..1535
    u64*   sW1ad = (u64*)(sh + 1536);   // 24 u64: {W1·a_src1, W1·a_dst1}[s]     floats 1536..1583
    u64*   sW2p  = (u64*)(sh + 1584);   // [32][25] u64: {W2[2j][o],W2[2j+1][o]} floats 1584..3183
    float* sW2a  = sh + 3184;           // 64
    float* sW2d  = sh + 3248;           // 64
    float* sB1   = sh + 3312;           // 64
    float* sB2   = sh + 3376;           // 24
    float* sCnt  = sh + 3400;           // 14*17 = 238 (pad 240) -> 3640

    const int tid = threadIdx.x;

    // ---- phase A: bulk loads ----
    for (int i = tid; i < 768; i += blockDim.x) {
        int s_ = i >> 5, l = i & 31;
        sW1p[i] = pk2(W1[s_ * GH + l], W1[s_ * GH + 32 + l]);
    }
    for (int i = tid; i < 768; i += blockDim.x) {
        int j = i / 24, o = i - j * 24;
        sW2p[j * 25 + o] = pk2(W2[(2 * j) * SEQ + o], W2[(2 * j + 1) * SEQ + o]);
    }
    if (tid < 64) sB1[tid] = b1[tid];
    if (tid < 24) sB2[tid] = b2[tid];
    for (int i = tid; i < 240; i += blockDim.x) sCnt[i] = 0.f;
    __syncthreads();

    // ---- phase B: attention-vector precompute + edge-count matrix ----
    if (tid < 24) {
        float s_ = 0.f, d_ = 0.f;
        #pragma unroll
        for (int f = 0; f < GH; f++) {
            float w = W1[tid * GH + f];
            s_ += w * as1[f];
            d_ += w * ad1[f];
        }
        sW1ad[tid] = pk2(s_, d_);
    } else if (tid < 88) {
        int f = tid - 24;
        float s_ = 0.f, d_ = 0.f;
        #pragma unroll
        for (int o = 0; o < SEQ; o++) {
            float w = W2[f * SEQ + o];
            s_ += w * as2[o];
            d_ += w * ad2[o];
        }
        sW2a[f] = s_; sW2d[f] = d_;
    } else if (tid >= 176) {
        for (int e = tid - 176; e < NE; e += 16) {
            int s_, d_;
            if (e < E0) { s_ = ei[e]; d_ = ei[E0 + e]; }
            else        { s_ = e - E0; d_ = s_; }
            atomicAdd(&sCnt[d_ * 17 + s_], 1.0f);
        }
    }
    __syncthreads();

    const int warp = tid >> 5, lane = tid & 31;
    const int b = blockIdx.x * WARPS_A + warp;
    if (b >= BATCH) return;

    float* pw  = sh + BC_SIZE + warp * PW_SIZE;
    u64*   xu  = (u64*)pw;      // [14][24] duplicated x  (dead after step 3)
    float* g1s = pw;            // [14][68] g1, later t   (overlays xu)
    float* Aw  = pw + 952;      // [14][16]
    float* vas = pw + 1176;     // 16
    float* vad = pw + 1192;     // 16

    // ---- 1. load x[b] -> duplicated transposed xu[n][s] = {x,x} ----
    {
        const float4* xb4 = (const float4*)(x + (size_t)b * (SEQ * NN));
        for (int i4 = lane; i4 < 84; i4 += 32) {
            float4 v = xb4[i4];
            int base = i4 * 4;
            int s0 = base / NN,       n0 = base - s0 * NN;
            int s1 = (base+1) / NN,   n1 = (base+1) - s1 * NN;
            int s2_ = (base+2) / NN,  n2 = (base+2) - s2_ * NN;
            int s3 = (base+3) / NN,   n3 = (base+3) - s3 * NN;
            xu[n0 * 24 + s0]  = pk2(v.x, v.x);
            xu[n1 * 24 + s1]  = pk2(v.y, v.y);
            xu[n2 * 24 + s2_] = pk2(v.z, v.z);
            xu[n3 * 24 + s3]  = pk2(v.w, v.w);
        }
    }
    __syncwarp();

    // ---- 2. layer-1 attention dots (packed, paired loads) ----
    if (lane < NN) {
        u64 acc = 0ull;
        #pragma unroll
        for (int s = 0; s < SEQ; s += 2) {
            ulonglong2 xx = *(const ulonglong2*)&xu[lane * 24 + s];
            ulonglong2 wv = *(const ulonglong2*)&sW1ad[s];
            acc = ff2(xx.x, wv.x, ff2(xx.y, wv.y, acc));
        }
        float a_, d_; upk2(acc, a_, d_);
        vas[lane] = a_; vad[lane] = d_;
    }

    // ---- 3. h1 packed in registers (paired s iterations) ----
    u64 h2[NN];
    #pragma unroll
    for (int n = 0; n < NN; n++) h2[n] = 0ull;
    #pragma unroll
    for (int s = 0; s < SEQ; s += 2) {
        u64 wv0 = sW1p[s * 32 + lane];
        u64 wv1 = sW1p[(s + 1) * 32 + lane];
        #pragma unroll
        for (int n = 0; n < NN; n++) {
            ulonglong2 xx = *(const ulonglong2*)&xu[n * 24 + s];
            h2[n] = ff2(xx.x, wv0, ff2(xx.y, wv1, h2[n]));
        }
    }
    float h1a[NN], h1b[NN];
    #pragma unroll
    for (int n = 0; n < NN; n++) upk2(h2[n], h1a[n], h1b[n]);
    __syncwarp();

    // ---- 4. softmax layer 1 -> Aw, vas := 1/sum ----
    if (lane < NN) {
        const float dn = vad[lane];
        float al[NN], mx = -1e30f;
        #pragma unroll
        for (int m = 0; m < NN; m++) {
            float c = sCnt[lane * 17 + m];
            float v = vas[m] + dn;
            v = (v >= 0.f) ? v : 0.2f * v;
            al[m] = v;
            if (c > 0.f) mx = fmaxf(mx, v);
        }
        float ssum = 0.f;
        #pragma unroll
        for (int m = 0; m < NN; m++) {
            float c = sCnt[lane * 17 + m];
            float e = c * __expf(al[m] - mx);
            ssum += e;
            Aw[lane * 16 + m] = e;
        }
        Aw[lane * 16 + 14] = 0.f;
        Aw[lane * 16 + 15] = 0.f;
        vas[lane] = 1.0f / ssum;
    }
    __syncwarp();

    // ---- 5. aggregate layer 1 + bias + ELU; stash g1 ----
    float g1a[NN], g1b[NN];
    {
        const float bb0 = sB1[lane], bb1 = sB1[32 + lane];
        #pragma unroll
        for (int n = 0; n < NN; n++) {
            float4 A0 = *(const float4*)&Aw[n * 16 + 0];
            float4 A1 = *(const float4*)&Aw[n * 16 + 4];
            float4 A2 = *(const float4*)&Aw[n * 16 + 8];
            float2 A3 = *(const float2*)&Aw[n * 16 + 12];
            float a0 = A0.x*h1a[0] + A0.y*h1a[1] + A0.z*h1a[2] + A0.w*h1a[3]
                     + A1.x*h1a[4] + A1.y*h1a[5] + A1.z*h1a[6] + A1.w*h1a[7]
                     + A2.x*h1a[8] + A2.y*h1a[9] + A2.z*h1a[10]+ A2.w*h1a[11]
                     + A3.x*h1a[12]+ A3.y*h1a[13];
            float a1 = A0.x*h1b[0] + A0.y*h1b[1] + A0.z*h1b[2] + A0.w*h1b[3]
                     + A1.x*h1b[4] + A1.y*h1b[5] + A1.z*h1b[6] + A1.w*h1b[7]
                     + A2.x*h1b[8] + A2.y*h1b[9] + A2.z*h1b[10]+ A2.w*h1b[11]
                     + A3.x*h1b[12]+ A3.y*h1b[13];
            float inv = vas[n];
            float v0 = a0 * inv + bb0;
            float v1 = a1 * inv + bb1;
            v0 = (v0 > 0.f) ? v0 : (__expf(v0) - 1.f);
            v1 = (v1 > 0.f) ? v1 : (__expf(v1) - 1.f);
            g1a[n] = v0; g1b[n] = v1;
            g1s[n * 68 + lane]      = v0;
            g1s[n * 68 + 32 + lane] = v1;
        }
    }
    __syncwarp();

    // ---- 6. layer-2 attention dots ----
    if (lane < NN) {
        float s_ = 0.f, d_ = 0.f;
        #pragma unroll
        for (int j = 0; j < 16; j++) {
            float4 g = *(const float4*)&g1s[lane * 68 + 4 * j];
            float4 wa = *(const float4*)&sW2a[4 * j];
            float4 wd = *(const float4*)&sW2d[4 * j];
            s_ += g.x * wa.x + g.y * wa.y + g.z * wa.z + g.w * wa.w;
            d_ += g.x * wd.x + g.y * wd.y + g.z * wd.z + g.w * wd.w;
        }
        vas[lane] = s_; vad[lane] = d_;
    }
    __syncwarp();

    // ---- 7. softmax layer 2 -> Aw, vas := 1/sum ----
    if (lane < NN) {
        const float dn = vad[lane];
        float al[NN], mx = -1e30f;
        #pragma unroll
        for (int m = 0; m < NN; m++) {
            float c = sCnt[lane * 17 + m];
            float v = vas[m] + dn;
            v = (v >= 0.f) ? v : 0.2f * v;
            al[m] = v;
            if (c > 0.f) mx = fmaxf(mx, v);
        }
        float ssum = 0.f;
        #pragma unroll
        for (int m = 0; m < NN; m++) {
            float c = sCnt[lane * 17 + m];
            float e = c * __expf(al[m] - mx);
            ssum += e;
            Aw[lane * 16 + m] = e;
        }
        Aw[lane * 16 + 14] = 0.f;
        Aw[lane * 16 + 15] = 0.f;
        vas[lane] = 1.0f / ssum;
    }
    __syncwarp();

    // ---- 8. t = A2·g1 (registers), scaled; stash ----
    #pragma unroll
    for (int n = 0; n < NN; n++) {
        float4 A0 = *(const float4*)&Aw[n * 16 + 0];
        float4 A1 = *(const float4*)&Aw[n * 16 + 4];
        float4 A2 = *(const float4*)&Aw[n * 16 + 8];
        float2 A3 = *(const float2*)&Aw[n * 16 + 12];
        float a0 = A0.x*g1a[0] + A0.y*g1a[1] + A0.z*g1a[2] + A0.w*g1a[3]
                 + A1.x*g1a[4] + A1.y*g1a[5] + A1.z*g1a[6] + A1.w*g1a[7]
                 + A2.x*g1a[8] + A2.y*g1a[9] + A2.z*g1a[10]+ A2.w*g1a[11]
                 + A3.x*g1a[12]+ A3.y*g1a[13];
        float a1 = A0.x*g1b[0] + A0.y*g1b[1] + A0.z*g1b[2] + A0.w*g1b[3]
                 + A1.x*g1b[4] + A1.y*g1b[5] + A1.z*g1b[6] + A1.w*g1b[7]
                 + A2.x*g1b[8] + A2.y*g1b[9] + A2.z*g1b[10]+ A2.w*g1b[11]
                 + A3.x*g1b[12]+ A3.y*g1b[13];
        float inv = vas[n];
        g1s[n * 68 + lane]      = a0 * inv;
        g1s[n * 68 + 32 + lane] = a1 * inv;
    }
    __syncwarp();

    // ---- 9. g2 = t·W2 + b2 -> g_mid[n][b][o] (packed FFMA2, broadcast weights) ----
    {
        const int o = (lane < SEQ) ? lane : 0;
        u64 acc2[NN];
        #pragma unroll
        for (int n = 0; n < NN; n++) acc2[n] = 0ull;
        #pragma unroll
        for (int c = 0; c < 4; c++) {
            u64 w2r[8];
            #pragma unroll
            for (int j = 0; j < 8; j++) w2r[j] = sW2p[(c * 8 + j) * 25 + o];
            #pragma unroll
            for (int n = 0; n < NN; n++) {
                const ulonglong2* tp = (const ulonglong2*)&g1s[n * 68 + c * 16];
                ulonglong2 t0 = tp[0], t1 = tp[1], t2 = tp[2], t3 = tp[3];
                u64 a = acc2[n];
                a = ff2(t0.x, w2r[0], a); a = ff2(t0.y, w2r[1], a);
                a = ff2(t1.x, w2r[2], a); a = ff2(t1.y, w2r[3], a);
                a = ff2(t2.x, w2r[4], a); a = ff2(t2.y, w2r[5], a);
                a = ff2(t3.x, w2r[6], a); a = ff2(t3.y, w2r[7], a);
                acc2[n] = a;
            }
        }
        if (lane < SEQ) {
            const float bb2 = sB2[o];
            #pragma unroll
            for (int n = 0; n < NN; n++) {
                float lo, hi; upk2(acc2[n], lo, hi);
                g_mid[(size_t)n * BATCH * SEQ + (size_t)b * SEQ + lane] = lo + hi + bb2;
            }
        }
    }
}

// ============================ MLP kernel (round-8 exact, 120.6 us) ===========
#define MW 4
#define MLP_SMEM_U64 (1600 + 1536 + 24 + MW * 800)
#define MLP_SMEM_BYTES (MLP_SMEM_U64 * 8)    // 50,880 B

__global__ void __launch_bounds__(32 * MW, 4)
mlp_kernel(const float* __restrict__ f1w, const float* __restrict__ f1b,
           const float* __restrict__ f2w, const float* __restrict__ f2b,
           float* __restrict__ out)
{
    extern __shared__ u64 dsm[];
    u64* sw1 = dsm;              // [25][64]: s rows duplicated {w,w}; row 24 = {b1,b1}
    u64* sw2 = dsm + 1600;       // [64][24]: {w2[f][o], w2[f][o]}
    u64* sb2 = dsm + 3136;       // 24: {b2[o], b2[o]}

    const int n   = blockIdx.y;
    const int tid = threadIdx.x;

    const float* w1base = f1w + (size_t)n * SEQ * GH;
    for (int i = tid; i < SEQ * GH; i += 32 * MW) { float v = w1base[i]; sw1[i] = pk2(v, v); }
    const float* b1base = f1b + (size_t)n * GH;
    for (int i = tid; i < GH; i += 32 * MW)       { float v = b1base[i]; sw1[24 * 64 + i] = pk2(v, v); }
    const float* w2base = f2w + (size_t)n * GH * SEQ;
    for (int i = tid; i < GH * SEQ; i += 32 * MW) { float v = w2base[i]; sw2[i] = pk2(v, v); }
    if (tid < SEQ) { float v = f2b[(size_t)n * SEQ + tid]; sb2[tid] = pk2(v, v); }
    __syncthreads();

    const int warp = tid >> 5, lane = tid & 31;
    u64* gp = dsm + 3160 + warp * 800;       // [32][25] packed g, self-row only

    const int base = (blockIdx.x * MW + warp) * 64;
    const float* gb = g_mid + (size_t)n * BATCH * SEQ;

    {
        const float4* r0 = (const float4*)(gb + (size_t)(base + lane) * SEQ);
        const float4* r1 = (const float4*)(gb + (size_t)(base + 32 + lane) * SEQ);
        u64* gr = gp + lane * 25;
        #pragma unroll
        for (int j = 0; j < 6; j++) {
            float4 a = r0[j], c = r1[j];
            gr[4 * j + 0] = pk2(a.x, c.x);
            gr[4 * j + 1] = pk2(a.y, c.y);
            gr[4 * j + 2] = pk2(a.z, c.z);
            gr[4 * j + 3] = pk2(a.w, c.w);
        }
    }

    u64 acc[SEQ];
    #pragma unroll
    for (int o = 0; o < SEQ; o++) acc[o] = sb2[o];

    const u64* gr = gp + lane * 25;

    #pragma unroll 1
    for (int c = 0; c < 8; c++) {
        u64 h[8];
        #pragma unroll
        for (int j = 0; j < 4; j++) {
            ulonglong2 bb = *(const ulonglong2*)&sw1[24 * 64 + c * 8 + 2 * j];
            h[2 * j] = bb.x; h[2 * j + 1] = bb.y;
        }
        #pragma unroll
        for (int s = 0; s < SEQ; s++) {
            u64 gv = gr[s];
            #pragma unroll
            for (int j = 0; j < 4; j++) {
                ulonglong2 w = *(const ulonglong2*)&sw1[s * 64 + c * 8 + 2 * j];
                h[2 * j]     = ff2(gv, w.x, h[2 * j]);
                h[2 * j + 1] = ff2(gv, w.y, h[2 * j + 1]);
            }
        }
        #pragma unroll
        for (int j = 0; j < 8; j++) {
            float lo, hi; upk2(h[j], lo, hi);
            h[j] = pk2(fmaxf(lo, 0.f), fmaxf(hi, 0.f));
        }
        #pragma unroll
        for (int j = 0; j < 8; j++) {
            const int f = c * 8 + j;
            #pragma unroll
            for (int oo = 0; oo < 12; oo++) {
                ulonglong2 w = *(const ulonglong2*)&sw2[f * 24 + 2 * oo];
                acc[2 * oo]     = ff2(h[j], w.x, acc[2 * oo]);
                acc[2 * oo + 1] = ff2(h[j], w.y, acc[2 * oo + 1]);
            }
        }
    }

    float* ob0 = out + (size_t)n * BATCH * SEQ + (size_t)(base + lane) * SEQ;
    float* ob1 = ob0 + (size_t)32 * SEQ;
    #pragma unroll
    for (int j = 0; j < 6; j++) {
        float a0,a1,b0,b1v,c0,c1,d0,d1;
        upk2(acc[4*j+0], a0, a1);
        upk2(acc[4*j+1], b0, b1v);
        upk2(acc[4*j+2], c0, c1);
        upk2(acc[4*j+3], d0, d1);
        ((float4*)ob0)[j] = make_float4(a0, b0, c0, d0);
        ((float4*)ob1)[j] = make_float4(a1, b1v, c1, d1);
    }
}

extern "C" void kernel_launch(void* const* d_in, const int* in_sizes, int n_in,
                              void* d_out, int out_size)
{
    const float* x   = (const float*)d_in[0];
    const int*   ei  = (const int*)d_in[1];
    const float* W1  = (const float*)d_in[2];
    const float* as1 = (const float*)d_in[3];
    const float* ad1 = (const float*)d_in[4];
    const float* b1  = (const float*)d_in[5];
    const float* W2  = (const float*)d_in[6];
    const float* as2 = (const float*)d_in[7];
    const float* ad2 = (const float*)d_in[8];
    const float* b2  = (const float*)d_in[9];
    const float* f1w = (const float*)d_in[10];
    const float* f1b = (const float*)d_in[11];
    const float* f2w = (const float*)d_in[12];
    const float* f2b = (const float*)d_in[13];
    float* out = (float*)d_out;

    static int configured = 0;
    if (!configured) {
        cudaFuncSetAttribute((const void*)mlp_kernel,
                             cudaFuncAttributeMaxDynamicSharedMemorySize, MLP_SMEM_BYTES);
        configured = 1;
    }

    gat_kernel<<<(BATCH + WARPS_A - 1) / WARPS_A, 32 * WARPS_A, SH_BYTES>>>(
        x, ei, W1, as1, ad1, b1, W2, as2, ad2, b2);

    mlp_kernel<<<dim3(BATCH / (MW * 64), NN), 32 * MW, MLP_SMEM_BYTES>>>(
        f1w, f1b, f2w, f2b, out);
}

// round 17
// speedup vs baseline: 1.1107x; 1.0426x over previous
#include <cuda_runtime.h>
#include <math.h>

#define NN    14
#define SEQ   24
#define GH    64
#define E0    56
#define NE    70
#define BATCH 32768

// 44 MB intermediate in [node][batch][seq] layout (== output layout)
__device__ float g_mid[(size_t)NN * BATCH * SEQ];

// ---------------- f32x2 packed-math helpers (Blackwell FFMA2) ----------------
typedef unsigned long long u64;

__device__ __forceinline__ u64 pk2(float lo, float hi) {
    u64 r; asm("mov.b64 %0, {%1,%2};" : "=l"(r) : "f"(lo), "f"(hi)); return r;
}
__device__ __forceinline__ void upk2(u64 v, float& lo, float& hi) {
    asm("mov.b64 {%0,%1}, %2;" : "=f"(lo), "=f"(hi) : "l"(v));
}
__device__ __forceinline__ u64 ff2(u64 a, u64 b, u64 c) {   // {a.lo*b.lo+c.lo, a.hi*b.hi+c.hi}
    u64 d; asm("fma.rn.f32x2 %0, %1, %2, %3;" : "=l"(d) : "l"(a), "l"(b), "l"(c)); return d;
}

// ================================ GAT kernel =================================
// (round-8 exact: measured 236 us)
#define WARPS_A 6
#define PW_SIZE 1208
#define BC_SIZE 3640
#define SH_FLOATS (BC_SIZE + WARPS_A * PW_SIZE)
#define SH_BYTES  (SH_FLOATS * 4)      // 43,552 B < 48 KB

__global__ void __launch_bounds__(32 * WARPS_A)
gat_kernel(const float* __restrict__ x, const int* __restrict__ ei,
           const float* __restrict__ W1, const float* __restrict__ as1,
           const float* __restrict__ ad1, const float* __restrict__ b1,
           const float* __restrict__ W2, const float* __restrict__ as2,
           const float* __restrict__ ad2, const float* __restrict__ b2)
{
    extern __shared__ float sh[];
    u64*   sW1p  = (u64*)sh;            // 768 u64: {W1[s][l], W1[s][l+32]}      floats 0..1535
    u64*   sW1ad = (u64*)(sh + 1536);   // 24 u64: {W1·a_src1, W1·a_dst1}[s]     floats 1536..1583
    u64*   sW2p  = (u64*)(sh + 1584);   // [32][25] u64: {W2[2j][o],W2[2j+1][o]} floats 1584..3183
    float* sW2a  = sh + 3184;           // 64
    float* sW2d  = sh + 3248;           // 64
    float* sB1   = sh + 3312;           // 64
    float* sB2   = sh + 3376;           // 24
    float* sCnt  = sh + 3400;           // 14*17 = 238 (pad 240) -> 3640

    const int tid = threadIdx.x;

    // ---- phase A: bulk loads ----
    for (int i = tid; i < 768; i += blockDim.x) {
        int s_ = i >> 5, l = i & 31;
        sW1p[i] = pk2(W1[s_ * GH + l], W1[s_ * GH + 32 + l]);
    }
    for (int i = tid; i < 768; i += blockDim.x) {
        int j = i / 24, o = i - j * 24;
        sW2p[j * 25 + o] = pk2(W2[(2 * j) * SEQ + o], W2[(2 * j + 1) * SEQ + o]);
    }
    if (tid < 64) sB1[tid] = b1[tid];
    if (tid < 24) sB2[tid] = b2[tid];
    for (int i = tid; i < 240; i += blockDim.x) sCnt[i] = 0.f;
    __syncthreads();

    // ---- phase B: attention-vector precompute + edge-count matrix ----
    if (tid < 24) {
        float s_ = 0.f, d_ = 0.f;
        #pragma unroll
        for (int f = 0; f < GH; f++) {
            float w = W1[tid * GH + f];
            s_ += w * as1[f];
            d_ += w * ad1[f];
        }
        sW1ad[tid] = pk2(s_, d_);
    } else if (tid < 88) {
        int f = tid - 24;
        float s_ = 0.f, d_ = 0.f;
        #pragma unroll
        for (int o = 0; o < SEQ; o++) {
            float w = W2[f * SEQ + o];
            s_ += w * as2[o];
            d_ += w * ad2[o];
        }
        sW2a[f] = s_; sW2d[f] = d_;
    } else if (tid >= 176) {
        for (int e = tid - 176; e < NE; e += 16) {
            int s_, d_;
            if (e < E0) { s_ = ei[e]; d_ = ei[E0 + e]; }
            else        { s_ = e - E0; d_ = s_; }
            atomicAdd(&sCnt[d_ * 17 + s_], 1.0f);
        }
    }
    __syncthreads();

    const int warp = tid >> 5, lane = tid & 31;
    const int b = blockIdx.x * WARPS_A + warp;
    if (b >= BATCH) return;

    float* pw  = sh + BC_SIZE + warp * PW_SIZE;
    u64*   xu  = (u64*)pw;      // [14][24] duplicated x  (dead after step 3)
    float* g1s = pw;            // [14][68] g1, later t   (overlays xu)
    float* Aw  = pw + 952;      // [14][16]
    float* vas = pw + 1176;     // 16
    float* vad = pw + 1192;     // 16

    // ---- 1. load x[b] -> duplicated transposed xu[n][s] = {x,x} ----
    {
        const float4* xb4 = (const float4*)(x + (size_t)b * (SEQ * NN));
        for (int i4 = lane; i4 < 84; i4 += 32) {
            float4 v = xb4[i4];
            int base = i4 * 4;
            int s0 = base / NN,       n0 = base - s0 * NN;
            int s1 = (base+1) / NN,   n1 = (base+1) - s1 * NN;
            int s2_ = (base+2) / NN,  n2 = (base+2) - s2_ * NN;
            int s3 = (base+3) / NN,   n3 = (base+3) - s3 * NN;
            xu[n0 * 24 + s0]  = pk2(v.x, v.x);
            xu[n1 * 24 + s1]  = pk2(v.y, v.y);
            xu[n2 * 24 + s2_] = pk2(v.z, v.z);
            xu[n3 * 24 + s3]  = pk2(v.w, v.w);
        }
    }
    __syncwarp();

    // ---- 2. layer-1 attention dots (packed, paired loads) ----
    if (lane < NN) {
        u64 acc = 0ull;
        #pragma unroll
        for (int s = 0; s < SEQ; s += 2) {
            ulonglong2 xx = *(const ulonglong2*)&xu[lane * 24 + s];
            ulonglong2 wv = *(const ulonglong2*)&sW1ad[s];
            acc = ff2(xx.x, wv.x, ff2(xx.y, wv.y, acc));
        }
        float a_, d_; upk2(acc, a_, d_);
        vas[lane] = a_; vad[lane] = d_;
    }

    // ---- 3. h1 packed in registers (paired s iterations) ----
    u64 h2[NN];
    #pragma unroll
    for (int n = 0; n < NN; n++) h2[n] = 0ull;
    #pragma unroll
    for (int s = 0; s < SEQ; s += 2) {
        u64 wv0 = sW1p[s * 32 + lane];
        u64 wv1 = sW1p[(s + 1) * 32 + lane];
        #pragma unroll
        for (int n = 0; n < NN; n++) {
            ulonglong2 xx = *(const ulonglong2*)&xu[n * 24 + s];
            h2[n] = ff2(xx.x, wv0, ff2(xx.y, wv1, h2[n]));
        }
    }
    float h1a[NN], h1b[NN];
    #pragma unroll
    for (int n = 0; n < NN; n++) upk2(h2[n], h1a[n], h1b[n]);
    __syncwarp();

    // ---- 4. softmax layer 1 -> Aw, vas := 1/sum ----
    if (lane < NN) {
        const float dn = vad[lane];
        float al[NN], mx = -1e30f;
        #pragma unroll
        for (int m = 0; m < NN; m++) {
            float c = sCnt[lane * 17 + m];
            float v = vas[m] + dn;
            v = (v >= 0.f) ? v : 0.2f * v;
            al[m] = v;
            if (c > 0.f) mx = fmaxf(mx, v);
        }
        float ssum = 0.f;
        #pragma unroll
        for (int m = 0; m < NN; m++) {
            float c = sCnt[lane * 17 + m];
            float e = c * __expf(al[m] - mx);
            ssum += e;
            Aw[lane * 16 + m] = e;
        }
        Aw[lane * 16 + 14] = 0.f;
        Aw[lane * 16 + 15] = 0.f;
        vas[lane] = 1.0f / ssum;
    }
    __syncwarp();

    // ---- 5. aggregate layer 1 + bias + ELU; stash g1 ----
    float g1a[NN], g1b[NN];
    {
        const float bb0 = sB1[lane], bb1 = sB1[32 + lane];
        #pragma unroll
        for (int n = 0; n < NN; n++) {
            float4 A0 = *(const float4*)&Aw[n * 16 + 0];
            float4 A1 = *(const float4*)&Aw[n * 16 + 4];
            float4 A2 = *(const float4*)&Aw[n * 16 + 8];
            float2 A3 = *(const float2*)&Aw[n * 16 + 12];
            float a0 = A0.x*h1a[0] + A0.y*h1a[1] + A0.z*h1a[2] + A0.w*h1a[3]
                     + A1.x*h1a[4] + A1.y*h1a[5] + A1.z*h1a[6] + A1.w*h1a[7]
                     + A2.x*h1a[8] + A2.y*h1a[9] + A2.z*h1a[10]+ A2.w*h1a[11]
                     + A3.x*h1a[12]+ A3.y*h1a[13];
            float a1 = A0.x*h1b[0] + A0.y*h1b[1] + A0.z*h1b[2] + A0.w*h1b[3]
                     + A1.x*h1b[4] + A1.y*h1b[5] + A1.z*h1b[6] + A1.w*h1b[7]
                     + A2.x*h1b[8] + A2.y*h1b[9] + A2.z*h1b[10]+ A2.w*h1b[11]
                     + A3.x*h1b[12]+ A3.y*h1b[13];
            float inv = vas[n];
            float v0 = a0 * inv + bb0;
            float v1 = a1 * inv + bb1;
            v0 = (v0 > 0.f) ? v0 : (__expf(v0) - 1.f);
            v1 = (v1 > 0.f) ? v1 : (__expf(v1) - 1.f);
            g1a[n] = v0; g1b[n] = v1;
            g1s[n * 68 + lane]      = v0;
            g1s[n * 68 + 32 + lane] = v1;
        }
    }
    __syncwarp();

    // ---- 6. layer-2 attention dots ----
    if (lane < NN) {
        float s_ = 0.f, d_ = 0.f;
        #pragma unroll
        for (int j = 0; j < 16; j++) {
            float4 g = *(const float4*)&g1s[lane * 68 + 4 * j];
            float4 wa = *(const float4*)&sW2a[4 * j];
            float4 wd = *(const float4*)&sW2d[4 * j];
            s_ += g.x * wa.x + g.y * wa.y + g.z * wa.z + g.w * wa.w;
            d_ += g.x * wd.x + g.y * wd.y + g.z * wd.z + g.w * wd.w;
        }
        vas[lane] = s_; vad[lane] = d_;
    }
    __syncwarp();

    // ---- 7. softmax layer 2 -> Aw, vas := 1/sum ----
    if (lane < NN) {
        const float dn = vad[lane];
        float al[NN], mx = -1e30f;
        #pragma unroll
        for (int m = 0; m < NN; m++) {
            float c = sCnt[lane * 17 + m];
            float v = vas[m] + dn;
            v = (v >= 0.f) ? v : 0.2f * v;
            al[m] = v;
            if (c > 0.f) mx = fmaxf(mx, v);
        }
        float ssum = 0.f;
        #pragma unroll
        for (int m = 0; m < NN; m++) {
            float c = sCnt[lane * 17 + m];
            float e = c * __expf(al[m] - mx);
            ssum += e;
            Aw[lane * 16 + m] = e;
        }
        Aw[lane * 16 + 14] = 0.f;
        Aw[lane * 16 + 15] = 0.f;
        vas[lane] = 1.0f / ssum;
    }
    __syncwarp();

    // ---- 8. t = A2·g1 (registers), scaled; stash ----
    #pragma unroll
    for (int n = 0; n < NN; n++) {
        float4 A0 = *(const float4*)&Aw[n * 16 + 0];
        float4 A1 = *(const float4*)&Aw[n * 16 + 4];
        float4 A2 = *(const float4*)&Aw[n * 16 + 8];
        float2 A3 = *(const float2*)&Aw[n * 16 + 12];
        float a0 = A0.x*g1a[0] + A0.y*g1a[1] + A0.z*g1a[2] + A0.w*g1a[3]
                 + A1.x*g1a[4] + A1.y*g1a[5] + A1.z*g1a[6] + A1.w*g1a[7]
                 + A2.x*g1a[8] + A2.y*g1a[9] + A2.z*g1a[10]+ A2.w*g1a[11]
                 + A3.x*g1a[12]+ A3.y*g1a[13];
        float a1 = A0.x*g1b[0] + A0.y*g1b[1] + A0.z*g1b[2] + A0.w*g1b[3]
                 + A1.x*g1b[4] + A1.y*g1b[5] + A1.z*g1b[6] + A1.w*g1b[7]
                 + A2.x*g1b[8] + A2.y*g1b[9] + A2.z*g1b[10]+ A2.w*g1b[11]
                 + A3.x*g1b[12]+ A3.y*g1b[13];
        float inv = vas[n];
        g1s[n * 68 + lane]      = a0 * inv;
        g1s[n * 68 + 32 + lane] = a1 * inv;
    }
    __syncwarp();

    // ---- 9. g2 = t·W2 + b2 -> g_mid[n][b][o] (packed FFMA2, broadcast weights) ----
    {
        const int o = (lane < SEQ) ? lane : 0;
        u64 acc2[NN];
        #pragma unroll
        for (int n = 0; n < NN; n++) acc2[n] = 0ull;
        #pragma unroll
        for (int c = 0; c < 4; c++) {
            u64 w2r[8];
            #pragma unroll
            for (int j = 0; j < 8; j++) w2r[j] = sW2p[(c * 8 + j) * 25 + o];
            #pragma unroll
            for (int n = 0; n < NN; n++) {
                const ulonglong2* tp = (const ulonglong2*)&g1s[n * 68 + c * 16];
                ulonglong2 t0 = tp[0], t1 = tp[1], t2 = tp[2], t3 = tp[3];
                u64 a = acc2[n];
                a = ff2(t0.x, w2r[0], a); a = ff2(t0.y, w2r[1], a);
                a = ff2(t1.x, w2r[2], a); a = ff2(t1.y, w2r[3], a);
                a = ff2(t2.x, w2r[4], a); a = ff2(t2.y, w2r[5], a);
                a = ff2(t3.x, w2r[6], a); a = ff2(t3.y, w2r[7], a);
                acc2[n] = a;
            }
        }
        if (lane < SEQ) {
            const float bb2 = sB2[o];
            #pragma unroll
            for (int n = 0; n < NN; n++) {
                float lo, hi; upk2(acc2[n], lo, hi);
                g_mid[(size_t)n * BATCH * SEQ + (size_t)b * SEQ + lane] = lo + hi + bb2;
            }
        }
    }
}

// ============================ MLP kernel (round-8 body, MW=8 staging amortization)
#define MW 8
#define MLP_SMEM_U64 (1600 + 1536 + 24 + MW * 800)
#define MLP_SMEM_BYTES (MLP_SMEM_U64 * 8)    // 76,480 B -> 2 blocks/SM, 16 warps

__global__ void __launch_bounds__(32 * MW, 2)
mlp_kernel(const float* __restrict__ f1w, const float* __restrict__ f1b,
           const float* __restrict__ f2w, const float* __restrict__ f2b,
           float* __restrict__ out)
{
    extern __shared__ u64 dsm[];
    u64* sw1 = dsm;              // [25][64]: s rows duplicated {w,w}; row 24 = {b1,b1}
    u64* sw2 = dsm + 1600;       // [64][24]: {w2[f][o], w2[f][o]}
    u64* sb2 = dsm + 3136;       // 24: {b2[o], b2[o]}

    const int n   = blockIdx.y;
    const int tid = threadIdx.x;

    const float* w1base = f1w + (size_t)n * SEQ * GH;
    for (int i = tid; i < SEQ * GH; i += 32 * MW) { float v = w1base[i]; sw1[i] = pk2(v, v); }
    const float* b1base = f1b + (size_t)n * GH;
    for (int i = tid; i < GH; i += 32 * MW)       { float v = b1base[i]; sw1[24 * 64 + i] = pk2(v, v); }
    const float* w2base = f2w + (size_t)n * GH * SEQ;
    for (int i = tid; i < GH * SEQ; i += 32 * MW) { float v = w2base[i]; sw2[i] = pk2(v, v); }
    if (tid < SEQ) { float v = f2b[(size_t)n * SEQ + tid]; sb2[tid] = pk2(v, v); }
    __syncthreads();

    const int warp = tid >> 5, lane = tid & 31;
    u64* gp = dsm + 3160 + warp * 800;       // [32][25] packed g, self-row only

    const int base = (blockIdx.x * MW + warp) * 64;
    const float* gb = g_mid + (size_t)n * BATCH * SEQ;

    {
        const float4* r0 = (const float4*)(gb + (size_t)(base + lane) * SEQ);
        const float4* r1 = (const float4*)(gb + (size_t)(base + 32 + lane) * SEQ);
        u64* gr = gp + lane * 25;
        #pragma unroll
        for (int j = 0; j < 6; j++) {
            float4 a = r0[j], c = r1[j];
            gr[4 * j + 0] = pk2(a.x, c.x);
            gr[4 * j + 1] = pk2(a.y, c.y);
            gr[4 * j + 2] = pk2(a.z, c.z);
            gr[4 * j + 3] = pk2(a.w, c.w);
        }
    }

    u64 acc[SEQ];
    #pragma unroll
    for (int o = 0; o < SEQ; o++) acc[o] = sb2[o];

    const u64* gr = gp + lane * 25;

    #pragma unroll 1
    for (int c = 0; c < 8; c++) {
        u64 h[8];
        #pragma unroll
        for (int j = 0; j < 4; j++) {
            ulonglong2 bb = *(const ulonglong2*)&sw1[24 * 64 + c * 8 + 2 * j];
            h[2 * j] = bb.x; h[2 * j + 1] = bb.y;
        }
        #pragma unroll
        for (int s = 0; s < SEQ; s++) {
            u64 gv = gr[s];
            #pragma unroll
            for (int j = 0; j < 4; j++) {
                ulonglong2 w = *(const ulonglong2*)&sw1[s * 64 + c * 8 + 2 * j];
                h[2 * j]     = ff2(gv, w.x, h[2 * j]);
                h[2 * j + 1] = ff2(gv, w.y, h[2 * j + 1]);
            }
        }
        #pragma unroll
        for (int j = 0; j < 8; j++) {
            float lo, hi; upk2(h[j], lo, hi);
            h[j] = pk2(fmaxf(lo, 0.f), fmaxf(hi, 0.f));
        }
        #pragma unroll
        for (int j = 0; j < 8; j++) {
            const int f = c * 8 + j;
            #pragma unroll
            for (int oo = 0; oo < 12; oo++) {
                ulonglong2 w = *(const ulonglong2*)&sw2[f * 24 + 2 * oo];
                acc[2 * oo]     = ff2(h[j], w.x, acc[2 * oo]);
                acc[2 * oo + 1] = ff2(h[j], w.y, acc[2 * oo + 1]);
            }
        }
    }

    float* ob0 = out + (size_t)n * BATCH * SEQ + (size_t)(base + lane) * SEQ;
    float* ob1 = ob0 + (size_t)32 * SEQ;
    #pragma unroll
    for (int j = 0; j < 6; j++) {
        float a0,a1,b0,b1v,c0,c1,d0,d1;
        upk2(acc[4*j+0], a0, a1);
        upk2(acc[4*j+1], b0, b1v);
        upk2(acc[4*j+2], c0, c1);
        upk2(acc[4*j+3], d0, d1);
        ((float4*)ob0)[j] = make_float4(a0, b0, c0, d0);
        ((float4*)ob1)[j] = make_float4(a1, b1v, c1, d1);
    }
}

extern "C" void kernel_launch(void* const* d_in, const int* in_sizes, int n_in,
                              void* d_out, int out_size)
{
    const float* x   = (const float*)d_in[0];
    const int*   ei  = (const int*)d_in[1];
    const float* W1  = (const float*)d_in[2];
    const float* as1 = (const float*)d_in[3];
    const float* ad1 = (const float*)d_in[4];
    const float* b1  = (const float*)d_in[5];
    const float* W2  = (const float*)d_in[6];
    const float* as2 = (const float*)d_in[7];
    const float* ad2 = (const float*)d_in[8];
    const float* b2  = (const float*)d_in[9];
    const float* f1w = (const float*)d_in[10];
    const float* f1b = (const float*)d_in[11];
    const float* f2w = (const float*)d_in[12];
    const float* f2b = (const float*)d_in[13];
    float* out = (float*)d_out;

    static int configured = 0;
    if (!configured) {
        cudaFuncSetAttribute((const void*)mlp_kernel,
                             cudaFuncAttributeMaxDynamicSharedMemorySize, MLP_SMEM_BYTES);
        configured = 1;
    }

    gat_kernel<<<(BATCH + WARPS_A - 1) / WARPS_A, 32 * WARPS_A, SH_BYTES>>>(
        x, ei, W1, as1, ad1, b1, W2, as2, ad2, b2);

    // 32768 / (8 warps * 64 samples) = 64 blocks per node
    mlp_kernel<<<dim3(BATCH / (MW * 64), NN), 32 * MW, MLP_SMEM_BYTES>>>(
        f1w, f1b, f2w, f2b, out);
}